// round 10
// baseline (speedup 1.0000x reference)
#include <cuda_runtime.h>

// ============================================================================
// 2-layer tanh RNN, B=32, L=2048, H=512 — v9: tf32 tensor cores (3xTF32)
// on the proven v8 persistent/flag skeleton.
//
// 128 persistent CTAs (1/SM), 512 threads (16 warps):
//   CTA 0..63   : layer 0 (A), output cols [cta*8, cta*8+8)
//   CTA 64..127 : layer 1 (B), cols [(cta-64)*8, ...)
// Per CTA per step: D[32 x 8] = act[32 x 512] @ W[512 x 8] (x2 sides) done
// with mma.sync.m16n8k8.tf32: warp w -> (ks = w>>1 in 0..7: K-chunk of 64,
// mt = w&1: rows mt*16..+16). 48 HMMA/warp/step (3xTF32: hh + lh + hl).
//
// Precision: 3xTF32. Activations are published PRE-SPLIT as float2(hi,lo)
// (hi = tf32-rounded value, lo = tf32-rounded residual) into g_ring0/g_ring1,
// so consumers just reinterpret bits — no per-consumer cvt. Weights split
// once into SMEM, pre-arranged in exact B-fragment order (LDS.64/frag).
// x (layer-0 input side) is loaded raw and split in-register (A only).
//
// Sync: identical to v8. flagAL/AH (A col-halves, tgt 32), flagB (tgt 64);
// low warps (ks<4, k<256) gate on AL, high on AH; leader warps 0/8 poll,
// BAR256 releases the half. A's ring0 slot reuse gated on flagB[t-8].
//
// Epilogue: warps STS their m16n8 partials -> __syncthreads -> threads
// 0..255 sum the 8 K-chunks, add bias, tanh, split, publish -> __syncthreads
// -> tid0 red.release flag.
// ============================================================================

#define BB 32
#define LL 2048
#define HH 512
#define GA 64
#define GB 64
#define NTHR 512

__device__ float2 g_ring0[8][BB][HH];   // layer-0 h, pre-split (hi,lo), 1 MB
__device__ float2 g_ring1[8][BB][HH];   // layer-1 h, pre-split (hi,lo), 1 MB
__device__ int    g_flagAL[LL];
__device__ int    g_flagAH[LL];
__device__ int    g_flagB[LL];

__device__ __forceinline__ int acq(const int* p) {
    int v;
    asm volatile("ld.acquire.gpu.global.b32 %0, [%1];" : "=r"(v) : "l"(p) : "memory");
    return v;
}
__device__ __forceinline__ void rel_add(int* p) {
    asm volatile("red.release.gpu.global.add.u32 [%0], %1;"
                 :: "l"(p), "r"(1u) : "memory");
}
#define BAR256(id) asm volatile("bar.sync %0, 256;" :: "r"(id) : "memory")

__device__ __forceinline__ unsigned tf32r(float f) {
    unsigned r;
    asm("cvt.rna.tf32.f32 %0, %1;" : "=r"(r) : "f"(f));
    return r;
}
__device__ __forceinline__ float uaf(unsigned u) { return __uint_as_float(u); }
__device__ __forceinline__ unsigned fau(float f) { return __float_as_uint(f); }

// D(m16n8) += A(m16k8,row) * B(k8n8,col), tf32 inputs, f32 accumulate.
__device__ __forceinline__ void mma8(float c[4], const unsigned a[4],
                                     unsigned b0, unsigned b1) {
    asm volatile(
        "mma.sync.aligned.m16n8k8.row.col.f32.tf32.tf32.f32 "
        "{%0,%1,%2,%3}, {%4,%5,%6,%7}, {%8,%9}, {%0,%1,%2,%3};"
        : "+f"(c[0]), "+f"(c[1]), "+f"(c[2]), "+f"(c[3])
        : "r"(a[0]), "r"(a[1]), "r"(a[2]), "r"(a[3]), "r"(b0), "r"(b1));
}

// init: zero flags; pre-split h0 initial states into ring slot 7 (= (0-1)&7).
__global__ void init_kernel(const float* __restrict__ h0) {
    int i = blockIdx.x * blockDim.x + threadIdx.x;
    if (i < LL) {
        g_flagAL[i] = 0; g_flagAH[i] = 0; g_flagB[i] = 0;
    } else if (i < LL + 2 * BB * HH) {
        int idx = i - LL;
        int l = idx >> 14, r = idx & 16383, b = r >> 9, k = r & 511;
        float v  = h0[idx];
        float hi = uaf(tf32r(v));
        float lo = uaf(tf32r(v - hi));
        if (l) g_ring1[7][b][k] = make_float2(hi, lo);
        else   g_ring0[7][b][k] = make_float2(hi, lo);
    }
}

__global__ __launch_bounds__(NTHR, 1) void rnn_kernel(
    const float* __restrict__ x,   const float* __restrict__ h0in,
    const float* __restrict__ Wi,  const float* __restrict__ bi,
    const float* __restrict__ Wh,  const float* __restrict__ bh,
    float* __restrict__ out, int write_final)
{
    extern __shared__ float sm[];
    float* sW    = sm;               // [4 blocks][64 gk][64] : s0hi,s0lo,s1hi,s1lo
    float* sPart = sm + 16384;       // [16][128] partials
    float* sBias = sm + 16384 + 2048;// [8]

    const int  cta   = blockIdx.x;
    const bool isA   = (cta < GA);
    const int  layer = isA ? 0 : 1;
    const int  c0    = (isA ? cta : cta - GA) * 8;
    const int  tid   = threadIdx.x;
    const int  w     = tid >> 5;
    const int  ln    = tid & 31;
    const int  ks    = w >> 1;       // K-chunk 0..7 (k in [ks*64, ks*64+64))
    const int  mt    = w & 1;        // m-tile: rows mt*16..mt*16+15
    const int  g     = ln >> 2;      // fragment groupID
    const int  t4    = ln & 3;       // fragment threadID-in-group

    // ---- split + stage weights into fragment-ordered SMEM (once) ----
    for (int idx = tid; idx < 4096; idx += NTHR) {
        int k = idx >> 3, c = idx & 7;
        int gk = k >> 3, k7 = k & 7, tq = k7 & 3, rr = k7 >> 2;
        int lane = (c << 2) | tq;
        int o = gk * 64 + lane * 2 + rr;
        float wi = Wi[(size_t)layer * HH * HH + (size_t)k * HH + c0 + c];
        float hi = uaf(tf32r(wi)), lo = uaf(tf32r(wi - hi));
        sW[o] = hi;  sW[4096 + o] = lo;
        float wh = Wh[(size_t)layer * HH * HH + (size_t)k * HH + c0 + c];
        hi = uaf(tf32r(wh)); lo = uaf(tf32r(wh - hi));
        sW[8192 + o] = hi;  sW[12288 + o] = lo;
    }
    if (tid < 8)
        sBias[tid] = bi[layer * HH + c0 + tid] + bh[layer * HH + c0 + tid];
    __syncthreads();

    const float* w0h = sW + ln * 2;            // + gk*64 : Wi hi
    const float* w0l = sW + 4096 + ln * 2;     // Wi lo
    const float* w1h = sW + 8192 + ln * 2;     // Wh hi
    const float* w1l = sW + 12288 + ln * 2;    // Wh lo

    const int r0 = mt * 16 + g;                // this lane's two A-frag rows
    const int r1 = r0 + 8;

    #pragma unroll 1
    for (int t = 0; t < LL; t++) {
        float ac0[4] = {0.f, 0.f, 0.f, 0.f};
        float ac1[4] = {0.f, 0.f, 0.f, 0.f};

        if (isA) {
            // ---- x side (ungated, raw fp32, split in-register) ----
            const float* px0 = x + (size_t)r0 * LL * HH + (size_t)t * HH;
            const float* px1 = x + (size_t)r1 * LL * HH + (size_t)t * HH;
            #pragma unroll
            for (int kt = 0; kt < 8; kt++) {
                int gk = ks * 8 + kt;
                int kk = gk * 8 + t4;
                float v0 = px0[kk], v1 = px1[kk], v2 = px0[kk + 4], v3 = px1[kk + 4];
                unsigned ah[4], al[4];
                ah[0] = tf32r(v0); al[0] = tf32r(v0 - uaf(ah[0]));
                ah[1] = tf32r(v1); al[1] = tf32r(v1 - uaf(ah[1]));
                ah[2] = tf32r(v2); al[2] = tf32r(v2 - uaf(ah[2]));
                ah[3] = tf32r(v3); al[3] = tf32r(v3 - uaf(ah[3]));
                float2 bhv = *(const float2*)(w0h + gk * 64);
                float2 blv = *(const float2*)(w0l + gk * 64);
                mma8(ac0, ah, fau(bhv.x), fau(bhv.y));
                mma8(ac0, al, fau(bhv.x), fau(bhv.y));
                mma8(ac0, ah, fau(blv.x), fau(blv.y));
            }
            // ---- wait (v8 pattern: half-flags, leader poll, BAR256) ----
            if (t >= 1) {
                if (w < 8) {
                    if (w == 0) {
                        if (t >= 8) { while (acq(&g_flagAL[t-1]) < 32 ||
                                             acq(&g_flagB[t-8]) < GB) {} }
                        else        { while (acq(&g_flagAL[t-1]) < 32) {} }
                    }
                    BAR256(1);
                } else {
                    if (w == 8) { while (acq(&g_flagAH[t-1]) < 32) {} }
                    BAR256(2);
                }
            }
            // ---- h side (pre-split ring0 slot (t-1)&7, weights Wh) ----
            const float2* hb = &g_ring0[(t - 1) & 7][0][0];
            #pragma unroll
            for (int kt = 0; kt < 8; kt++) {
                int gk = ks * 8 + kt;
                int kk = gk * 8 + t4;
                float2 f0 = __ldcg(&hb[r0 * HH + kk]);
                float2 f1 = __ldcg(&hb[r1 * HH + kk]);
                float2 f2 = __ldcg(&hb[r0 * HH + kk + 4]);
                float2 f3 = __ldcg(&hb[r1 * HH + kk + 4]);
                unsigned ah[4] = {fau(f0.x), fau(f1.x), fau(f2.x), fau(f3.x)};
                unsigned al[4] = {fau(f0.y), fau(f1.y), fau(f2.y), fau(f3.y)};
                float2 bhv = *(const float2*)(w1h + gk * 64);
                float2 blv = *(const float2*)(w1l + gk * 64);
                mma8(ac1, ah, fau(bhv.x), fau(bhv.y));
                mma8(ac1, al, fau(bhv.x), fau(bhv.y));
                mma8(ac1, ah, fau(blv.x), fau(blv.y));
            }
        } else {
            // ---- combined wait: own flagB[t-1] + A's half-flag for step t ----
            if (w < 8) {
                if (w == 0) {
                    if (t >= 1) { while (acq(&g_flagB[t-1]) < GB ||
                                         acq(&g_flagAL[t]) < 32) {} }
                    else        { while (acq(&g_flagAL[0]) < 32) {} }
                }
                BAR256(1);
            } else {
                if (w == 8) {
                    if (t >= 1) { while (acq(&g_flagB[t-1]) < GB ||
                                         acq(&g_flagAH[t]) < 32) {} }
                    else        { while (acq(&g_flagAH[0]) < 32) {} }
                }
                BAR256(2);
            }
            const float2* rb = &g_ring0[t & 7][0][0];        // h0[t] w/ Wi1
            const float2* hb = &g_ring1[(t - 1) & 7][0][0];  // h1[t-1] w/ Wh1
            #pragma unroll
            for (int kt = 0; kt < 8; kt++) {
                int gk = ks * 8 + kt;
                int kk = gk * 8 + t4;
                float2 e0 = __ldcg(&rb[r0 * HH + kk]);
                float2 e1 = __ldcg(&rb[r1 * HH + kk]);
                float2 e2 = __ldcg(&rb[r0 * HH + kk + 4]);
                float2 e3 = __ldcg(&rb[r1 * HH + kk + 4]);
                float2 f0 = __ldcg(&hb[r0 * HH + kk]);
                float2 f1 = __ldcg(&hb[r1 * HH + kk]);
                float2 f2 = __ldcg(&hb[r0 * HH + kk + 4]);
                float2 f3 = __ldcg(&hb[r1 * HH + kk + 4]);
                unsigned ah0[4] = {fau(e0.x), fau(e1.x), fau(e2.x), fau(e3.x)};
                unsigned al0[4] = {fau(e0.y), fau(e1.y), fau(e2.y), fau(e3.y)};
                unsigned ah1[4] = {fau(f0.x), fau(f1.x), fau(f2.x), fau(f3.x)};
                unsigned al1[4] = {fau(f0.y), fau(f1.y), fau(f2.y), fau(f3.y)};
                float2 b0h = *(const float2*)(w0h + gk * 64);
                float2 b0l = *(const float2*)(w0l + gk * 64);
                float2 b1h = *(const float2*)(w1h + gk * 64);
                float2 b1l = *(const float2*)(w1l + gk * 64);
                mma8(ac0, ah0, fau(b0h.x), fau(b0h.y));
                mma8(ac0, al0, fau(b0h.x), fau(b0h.y));
                mma8(ac0, ah0, fau(b0l.x), fau(b0l.y));
                mma8(ac1, ah1, fau(b1h.x), fau(b1h.y));
                mma8(ac1, al1, fau(b1h.x), fau(b1h.y));
                mma8(ac1, ah1, fau(b1l.x), fau(b1l.y));
            }
        }

        // ---- merge sides, store partials ----
        float4 o4;
        o4.x = ac0[0] + ac1[0]; o4.y = ac0[1] + ac1[1];
        o4.z = ac0[2] + ac1[2]; o4.w = ac0[3] + ac1[3];
        *(float4*)&sPart[(mt * 8 + ks) * 128 + ln * 4] = o4;
        __syncthreads();

        // ---- finalize: 256 threads, one output element each ----
        if (tid < 256) {
            int e   = tid;
            int emt = e >> 7, w7 = e & 127;
            int lane = w7 >> 2, rr = w7 & 3;
            int row = emt * 16 + (lane >> 2) + 8 * (rr >> 1);
            int col = (lane & 3) * 2 + (rr & 1);
            float s = 0.f;
            #pragma unroll
            for (int q = 0; q < 8; q++)
                s += sPart[(emt * 8 + q) * 128 + w7];
            float hv = tanhf(s + sBias[col]);
            float hif = uaf(tf32r(hv));
            float lof = uaf(tf32r(hv - hif));
            if (isA) {
                g_ring0[t & 7][row][c0 + col] = make_float2(hif, lof);
                if (write_final && t == LL - 1)
                    out[(size_t)BB * LL * HH + row * HH + c0 + col] = hv;
            } else {
                g_ring1[t & 7][row][c0 + col] = make_float2(hif, lof);
                out[(size_t)row * LL * HH + (size_t)t * HH + c0 + col] = hv;
                if (write_final && t == LL - 1)
                    out[(size_t)BB * LL * HH + BB * HH + row * HH + c0 + col] = hv;
            }
        }
        __syncthreads();
        if (tid == 0) {
            if (isA) rel_add(cta < 32 ? &g_flagAL[t] : &g_flagAH[t]);
            else     rel_add(&g_flagB[t]);
        }
    }
}

extern "C" void kernel_launch(void* const* d_in, const int* in_sizes, int n_in,
                              void* d_out, int out_size)
{
    const float* x  = (const float*)d_in[0];
    const float* h0 = (const float*)d_in[1];
    const float* Wi = (const float*)d_in[2];
    const float* bi = (const float*)d_in[3];
    const float* Wh = (const float*)d_in[4];
    const float* bh = (const float*)d_in[5];
    float* out = (float*)d_out;

    int write_final = (out_size >= BB * LL * HH + 2 * BB * HH) ? 1 : 0;

    size_t smem = (size_t)(16384 + 2048 + 8) * sizeof(float);   // ~73.8 KB
    cudaFuncSetAttribute(rnn_kernel,
                         cudaFuncAttributeMaxDynamicSharedMemorySize, (int)smem);

    int init_n = LL + 2 * BB * HH;
    init_kernel<<<(init_n + 255) / 256, 256>>>(h0);
    rnn_kernel<<<GA + GB, NTHR, smem>>>(x, h0, Wi, bi, Wh, bh, out, write_final);
}

// round 11
// speedup vs baseline: 1.9488x; 1.9488x over previous
#include <cuda_runtime.h>

// ============================================================================
// 2-layer tanh RNN, B=32, L=2048, H=512 — v10: v8 + software-pipelined x-side.
//
// 128 persistent CTAs (1/SM), 512 threads (16 warps):
//   CTA 0..63   : layer 0 (A), output cols [cta*8, cta*8+8)
//   CTA 64..127 : layer 1 (B), cols [(cta-64)*8, ...)
// Warp pair (wp, wp+8): rows 4wp..4wp+3; warp wp = K-half 0 (gates on AL),
// warp wp+8 = K-half 1 (gates on AH). Weights in SMEM (lane-interleaved,
// conflict-free LDS.128); K map k = 128*i4 + 4*ln + e. All v8-proven.
//
// v10 change — A's phase shift:
//   u(t) = x(t) @ Wi0 (per-CTA-local!) is computed 4 steps AHEAD, after the
//   publish, into a 4-deep per-thread register queue (same thread produces
//   and consumes its element; high-half contribution crosses via comb_u SMEM).
//   A's step: wait(own t-1) -> h-side -> reduce -> tanh(+u) -> PUBLISH EARLY
//   -> x-side u(t+4). A's publish lands ~1000 cyc earlier in its period, so
//   B's wait on flagA*[t] mostly disappears.
//   B reorders: ring side (gated on early flagA*[t]) FIRST, then flagB[t-1]
//   gate, then h1 side.
// Sync primitive unchanged: leader-warp poll (w0/w8) + half-CTA named
// barrier; publish = STG -> BAR256(1) -> tid0 red.release.gpu.add.
// Dataflow: L0 h -> 8-slot global ring (reuse gated on flagB[t-8]);
// L1 h -> d_out. Cross-SM reads via __ldcg. fp32 fma.rn.f32x2 numerics.
// ============================================================================

#define BB 32
#define LL 2048
#define HH 512
#define GA 64
#define GB 64
#define NTHR 512

__device__ float g_ring[8 * BB * HH];   // layer-0 h ring, 8 slots, 512 KB
__device__ int   g_flagAL[LL];          // A cols [0,256)   done at t (tgt 32)
__device__ int   g_flagAH[LL];          // A cols [256,512) done at t (tgt 32)
__device__ int   g_flagB[LL];           // B done at t (tgt 64)

__device__ __forceinline__ int acq(const int* p) {
    int v;
    asm volatile("ld.acquire.gpu.global.b32 %0, [%1];" : "=r"(v) : "l"(p) : "memory");
    return v;
}
__device__ __forceinline__ void rel_add(int* p) {
    asm volatile("red.release.gpu.global.add.u32 [%0], %1;"
                 :: "l"(p), "r"(1u) : "memory");
}
#define BAR256(id) asm volatile("bar.sync %0, 256;" :: "r"(id) : "memory")
#define BAR64(id)  asm volatile("bar.sync %0, 64;"  :: "r"(id) : "memory")

#define FMA2(d, a, w) asm volatile("fma.rn.f32x2 %0, %1, %2, %0;" \
                                   : "+l"(d) : "l"(a), "l"(w))

__device__ __forceinline__ unsigned long long pack2(float v) {
    unsigned long long r;
    asm("mov.b64 %0, {%1,%1};" : "=l"(r) : "f"(v));
    return r;
}

__global__ void zero_flags_kernel() {
    int i = blockIdx.x * blockDim.x + threadIdx.x;
    if (i < LL) { g_flagAL[i] = 0; g_flagAH[i] = 0; g_flagB[i] = 0; }
}

// Accumulate ONE K-half (hk = 0: k<256, hk = 1: k>=256) of one side into
// acc[16] (acc[b*4+q] packs cols (2q,2q+1) for row b0+b). 8 LDG.128 batched
// up front. Weights lane-interleaved: [(i4*4+e)*32+ln] = k = 128*i4+4*ln+e.
__device__ __forceinline__ void accum_half(
    unsigned long long acc[16],
    const ulonglong2* __restrict__ wA, const ulonglong2* __restrict__ wB,
    const float* __restrict__ p, long long stride, int b0, int ln,
    int hk, bool cg)
{
    float4 v[2][4];
    #pragma unroll
    for (int j = 0; j < 2; j++) {
        int i4 = 2 * hk + j;
        #pragma unroll
        for (int b = 0; b < 4; b++) {
            const float4* a = (const float4*)(p + (long long)(b0 + b) * stride
                                              + 128 * i4 + 4 * ln);
            v[j][b] = cg ? __ldcg(a) : *a;
        }
    }
    #pragma unroll
    for (int j = 0; j < 2; j++) {
        int i4 = 2 * hk + j;
        #pragma unroll
        for (int e = 0; e < 4; e++) {
            ulonglong2 a  = wA[(i4 * 4 + e) * 32 + ln];
            ulonglong2 bq = wB[(i4 * 4 + e) * 32 + ln];
            #pragma unroll
            for (int b = 0; b < 4; b++) {
                float xv = (e == 0) ? v[j][b].x : (e == 1) ? v[j][b].y
                         : (e == 2) ? v[j][b].z : v[j][b].w;
                unsigned long long xp = pack2(xv);
                FMA2(acc[b * 4 + 0], xp, a.x);
                FMA2(acc[b * 4 + 1], xp, a.y);
                FMA2(acc[b * 4 + 2], xp, bq.x);
                FMA2(acc[b * 4 + 3], xp, bq.y);
            }
        }
    }
}

// Per-warp transpose-reduce over the 32-lane K split (v8 verbatim).
__device__ __forceinline__ float reduce32(const unsigned long long acc[16],
                                          float* redw, int ln)
{
    #pragma unroll
    for (int i = 0; i < 16; i++) {
        float2 v = *reinterpret_cast<const float2*>(&acc[i]);
        int a = (i >> 2) * 8 + (i & 3) * 2;
        redw[ln * 33 + a]     = v.x;
        redw[ln * 33 + a + 1] = v.y;
    }
    __syncwarp();
    float s0 = 0.f, s1 = 0.f, s2 = 0.f, s3 = 0.f;
    #pragma unroll
    for (int a = 0; a < 32; a += 4) {
        s0 += redw[(a + 0) * 33 + ln];
        s1 += redw[(a + 1) * 33 + ln];
        s2 += redw[(a + 2) * 33 + ln];
        s3 += redw[(a + 3) * 33 + ln];
    }
    __syncwarp();   // redw reusable immediately after
    return (s0 + s1) + (s2 + s3);
}

__global__ __launch_bounds__(NTHR, 1) void rnn_kernel(
    const float* __restrict__ x,   const float* __restrict__ h0in,
    const float* __restrict__ Wi,  const float* __restrict__ bi,
    const float* __restrict__ Wh,  const float* __restrict__ bh,
    float* __restrict__ out, int write_final)
{
    extern __shared__ float smem[];
    ulonglong2* sWiA = (ulonglong2*)smem;      // [512] Wi cols 0-3
    ulonglong2* sWiB = sWiA + HH;              // [512] Wi cols 4-7
    ulonglong2* sWhA = sWiB + HH;
    ulonglong2* sWhB = sWhA + HH;
    float*      red    = (float*)(sWhB + HH);  // [16 warps][32][33]
    float*      comb_h = red + 16 * 32 * 33;   // [2][256] h-side pair combine
    float*      comb_u = comb_h + 2 * 256;     // [2][256] u-side pair combine

    const int  cta   = blockIdx.x;
    const bool isA   = (cta < GA);
    const int  layer = isA ? 0 : 1;
    const int  c0    = (isA ? cta : cta - GA) * 8;
    const int  tid   = threadIdx.x;
    const int  w     = tid >> 5;
    const int  ln    = tid & 31;
    const int  hk    = w >> 3;          // 0 = low K-half, 1 = high K-half
    const int  wp    = w & 7;           // pair index / low-warp id
    const int  b0    = 4 * wp;

    // ---- stage weight slices once ----
    {
        const float* wi_g = Wi + (size_t)layer * HH * HH + c0;
        const float* wh_g = Wh + (size_t)layer * HH * HH + c0;
        for (int k = tid; k < HH; k += NTHR) {
            int idx = ((k >> 7) * 4 + (k & 3)) * 32 + ((k >> 2) & 31);
            const ulonglong2* ri = (const ulonglong2*)(wi_g + (size_t)k * HH);
            const ulonglong2* rh = (const ulonglong2*)(wh_g + (size_t)k * HH);
            sWiA[idx] = ri[0];  sWiB[idx] = ri[1];
            sWhA[idx] = rh[0];  sWhB[idx] = rh[1];
        }
    }
    __syncthreads();    // one-time; loop has no CTA-wide barrier

    const int   myb  = b0 + (ln >> 3);
    const int   myc  = c0 + (ln & 7);
    const float bias = bi[layer * HH + myc] + bh[layer * HH + myc];
    float* redw = red + w * (32 * 33);
    const int ci = wp * 32 + ln;        // this thread's combine-slot index

    if (isA) {
        // ======================= LAYER 0 =======================
        // 4-deep register queue of u(t) = x(t)@Wi0 (low warps hold it).
        float uq0 = 0.f, uq1 = 0.f, uq2 = 0.f, uq3 = 0.f;

        // warm-up: u(0..3)
        #pragma unroll 1
        for (int tw = 0; tw < 4; tw++) {
            unsigned long long au[16];
            #pragma unroll
            for (int i = 0; i < 16; i++) au[i] = 0ull;
            accum_half(au, sWiA, sWiB, x + (long long)tw * HH,
                       (long long)LL * HH, b0, ln, hk, false);
            float pu = reduce32(au, redw, ln);
            if (hk) {
                comb_u[(tw & 1) * 256 + ci] = pu;
                BAR64(3 + wp);
            } else {
                BAR64(3 + wp);
                float uv = pu + comb_u[(tw & 1) * 256 + ci];
                if (tw == 0) uq0 = uv; else if (tw == 1) uq1 = uv;
                else if (tw == 2) uq2 = uv; else uq3 = uv;
            }
        }

        #pragma unroll 1
        for (int t = 0; t < LL; t++) {
            // ---- gated h-side (own group t-1) ----
            unsigned long long acc[16];
            #pragma unroll
            for (int i = 0; i < 16; i++) acc[i] = 0ull;
            if (t == 0) {
                accum_half(acc, sWhA, sWhB, h0in, HH, b0, ln, hk, false);
            } else {
                if (hk == 0) {
                    if (w == 0) {
                        if (t >= 8) { while (acq(&g_flagAL[t-1]) < 32 ||
                                             acq(&g_flagB[t-8]) < GB) {} }
                        else        { while (acq(&g_flagAL[t-1]) < 32) {} }
                    }
                    BAR256(1);
                } else {
                    if (w == 8) { while (acq(&g_flagAH[t-1]) < 32) {} }
                    BAR256(2);
                }
                accum_half(acc, sWhA, sWhB,
                           g_ring + ((t - 1) & 7) * (BB * HH), HH, b0, ln, hk, true);
            }
            float psum = reduce32(acc, redw, ln);

            // ---- combine, tanh(+u), PUBLISH EARLY ----
            if (hk) {
                comb_h[(t & 1) * 256 + ci] = psum;
                BAR64(3 + wp);
            } else {
                BAR64(3 + wp);
                float hval = tanhf(psum + comb_h[(t & 1) * 256 + ci]
                                   + uq0 + bias);
                g_ring[(t & 7) * (BB * HH) + myb * HH + myc] = hval;
                if (write_final && t == LL - 1)
                    out[(long long)BB * LL * HH + myb * HH + myc] = hval;
                BAR256(1);                  // low half: STGs issued
                if (tid == 0) rel_add(cta < 32 ? &g_flagAL[t] : &g_flagAH[t]);
            }

            // ---- x-side for step t+4 (off the critical path) ----
            float unew = 0.f;
            if (t + 4 < LL) {
                unsigned long long au[16];
                #pragma unroll
                for (int i = 0; i < 16; i++) au[i] = 0ull;
                accum_half(au, sWiA, sWiB, x + (long long)(t + 4) * HH,
                           (long long)LL * HH, b0, ln, hk, false);
                float pu = reduce32(au, redw, ln);
                if (hk) {
                    comb_u[(t & 1) * 256 + ci] = pu;
                    BAR64(3 + wp);
                } else {
                    BAR64(3 + wp);
                    unew = pu + comb_u[(t & 1) * 256 + ci];
                }
            }
            uq0 = uq1; uq1 = uq2; uq2 = uq3; uq3 = unew;
        }
    } else {
        // ======================= LAYER 1 =======================
        #pragma unroll 1
        for (int t = 0; t < LL; t++) {
            unsigned long long acc[16];
            #pragma unroll
            for (int i = 0; i < 16; i++) acc[i] = 0ull;

            // ---- ring side FIRST (A publishes early -> near-free gate) ----
            if (hk == 0) {
                if (w == 0) { while (acq(&g_flagAL[t]) < 32) {} }
                BAR256(1);
            } else {
                if (w == 8) { while (acq(&g_flagAH[t]) < 32) {} }
                BAR256(2);
            }
            accum_half(acc, sWiA, sWiB, g_ring + (t & 7) * (BB * HH),
                       HH, b0, ln, hk, true);

            // ---- own h1 side (gated on flagB[t-1]) ----
            if (t == 0) {
                accum_half(acc, sWhA, sWhB, h0in + BB * HH, HH, b0, ln, hk, false);
            } else {
                if (hk == 0) {
                    if (w == 0) { while (acq(&g_flagB[t-1]) < GB) {} }
                    BAR256(1);
                } else {
                    if (w == 8) { while (acq(&g_flagB[t-1]) < GB) {} }
                    BAR256(2);
                }
                accum_half(acc, sWhA, sWhB, out + (long long)(t - 1) * HH,
                           (long long)LL * HH, b0, ln, hk, true);
            }

            float psum = reduce32(acc, redw, ln);
            if (hk) {
                comb_h[(t & 1) * 256 + ci] = psum;
                BAR64(3 + wp);
            } else {
                BAR64(3 + wp);
                float hval = tanhf(psum + comb_h[(t & 1) * 256 + ci] + bias);
                out[(long long)myb * LL * HH + (long long)t * HH + myc] = hval;
                if (write_final && t == LL - 1)
                    out[(long long)BB * LL * HH + BB * HH + myb * HH + myc] = hval;
                BAR256(1);
                if (tid == 0) rel_add(&g_flagB[t]);
            }
        }
    }
}

extern "C" void kernel_launch(void* const* d_in, const int* in_sizes, int n_in,
                              void* d_out, int out_size)
{
    const float* x  = (const float*)d_in[0];
    const float* h0 = (const float*)d_in[1];
    const float* Wi = (const float*)d_in[2];
    const float* bi = (const float*)d_in[3];
    const float* Wh = (const float*)d_in[4];
    const float* bh = (const float*)d_in[5];
    float* out = (float*)d_out;

    int write_final = (out_size >= BB * LL * HH + 2 * BB * HH) ? 1 : 0;

    size_t smem = (size_t)(4 * HH * 16)                    // weights 32 KB
                + (size_t)(16 * 32 * 33) * sizeof(float)   // red    ~66 KB
                + (size_t)(4 * 256) * sizeof(float);       // comb_h/u 4 KB
    cudaFuncSetAttribute(rnn_kernel,
                         cudaFuncAttributeMaxDynamicSharedMemorySize, (int)smem);

    zero_flags_kernel<<<(LL + 255) / 256, 256>>>();
    rnn_kernel<<<GA + GB, NTHR, smem>>>(x, h0, Wi, bi, Wh, bh, out, write_final);
}